// round 2
// baseline (speedup 1.0000x reference)
#include <cuda_runtime.h>

#define TOK   4608      // n*H*W
#define NB    2
#define HH    48
#define WW    48
#define DM    256
#define NHEAD 4
#define EH    64
#define EPS   1e-6f

// ---------------- scratch (__device__ globals: allocation-free) ----------------
__device__ float g_scale[NB * DM];                    // (cond @ w_norm.T) + 1
__device__ float g_xn  [TOK * DM];                    // rms-normed x
__device__ float g_qkv [TOK * 3 * DM];                // qkv GEMM output
__device__ float g_q   [NB * NHEAD * HH * WW * EH];   // [b][h][i][j][e], rotary + /8
__device__ float g_k   [NB * NHEAD * HH * WW * EH];
__device__ float g_v   [NB * NHEAD * HH * WW * EH];
__device__ float g_o   [TOK * DM];                    // attn out, [token][h*64+e]

// ---------------- K0: scale[b][c] = dot(cond[b], w_norm[c]) + 1 ----------------
__global__ void k_scale(const float* __restrict__ cond, const float* __restrict__ w_norm) {
    int b = blockIdx.x, c = threadIdx.x;
    const float4* cv = (const float4*)(cond + b * DM);
    const float4* wv = (const float4*)(w_norm + c * DM);
    float s = 0.f;
#pragma unroll 16
    for (int k = 0; k < DM / 4; k++) {
        float4 a = cv[k], w = wv[k];
        s += a.x * w.x + a.y * w.y + a.z * w.z + a.w * w.w;
    }
    g_scale[b * DM + c] = s + 1.f;
}

// ---------------- K1: RMS norm per token ----------------
__global__ void k_rms(const float* __restrict__ x) {
    int t = blockIdx.x;
    int c = threadIdx.x;
    int b = t / (HH * WW);
    float v = x[t * DM + c];
    float sq = v * v;
#pragma unroll
    for (int o = 16; o > 0; o >>= 1) sq += __shfl_xor_sync(0xffffffffu, sq, o);
    __shared__ float ws[8];
    if ((c & 31) == 0) ws[c >> 5] = sq;
    __syncthreads();
    float tot = ws[0] + ws[1] + ws[2] + ws[3] + ws[4] + ws[5] + ws[6] + ws[7];
    float inv = rsqrtf(tot * (1.f / DM) + EPS);
    g_xn[t * DM + c] = v * g_scale[b * DM + c] * inv;
}

// ---------------- tiled fp32 NT GEMM: C[M,N] = A[M,K] * B[N,K]^T (+Sk) ----------------
__device__ __forceinline__ void gemm_nt(const float* __restrict__ A, const float* __restrict__ B,
                                        const float* __restrict__ Sk, float* __restrict__ C,
                                        int M, int Nn, int Kk) {
    __shared__ float As[64][17];
    __shared__ float Bs[64][17];
    int tid = threadIdx.x;
    int tx = tid & 15, ty = tid >> 4;
    int m0 = blockIdx.y * 64, n0 = blockIdx.x * 64;
    int lr = tid >> 2;            // 0..63
    int lc = (tid & 3) * 4;       // 0,4,8,12
    float acc[4][4] = {};
    for (int k0 = 0; k0 < Kk; k0 += 16) {
        float4 av = *(const float4*)(A + (size_t)(m0 + lr) * Kk + k0 + lc);
        float4 bv = *(const float4*)(B + (size_t)(n0 + lr) * Kk + k0 + lc);
        As[lr][lc + 0] = av.x; As[lr][lc + 1] = av.y; As[lr][lc + 2] = av.z; As[lr][lc + 3] = av.w;
        Bs[lr][lc + 0] = bv.x; Bs[lr][lc + 1] = bv.y; Bs[lr][lc + 2] = bv.z; Bs[lr][lc + 3] = bv.w;
        __syncthreads();
#pragma unroll
        for (int kk = 0; kk < 16; kk++) {
            float a[4], bb[4];
#pragma unroll
            for (int i = 0; i < 4; i++) a[i] = As[ty * 4 + i][kk];
#pragma unroll
            for (int j = 0; j < 4; j++) bb[j] = Bs[tx * 4 + j][kk];
#pragma unroll
            for (int i = 0; i < 4; i++)
#pragma unroll
                for (int j = 0; j < 4; j++) acc[i][j] += a[i] * bb[j];
        }
        __syncthreads();
    }
#pragma unroll
    for (int i = 0; i < 4; i++)
#pragma unroll
        for (int j = 0; j < 4; j++) {
            int m = m0 + ty * 4 + i, nn = n0 + tx * 4 + j;
            float r = acc[i][j];
            if (Sk) r += Sk[(size_t)m * Nn + nn];
            C[(size_t)m * Nn + nn] = r;
        }
}

__global__ void __launch_bounds__(256) k_gemm_qkv(const float* __restrict__ w_qkv) {
    gemm_nt(g_xn, w_qkv, nullptr, g_qkv, TOK, 3 * DM, DM);
}
__global__ void __launch_bounds__(256) k_gemm_out(const float* __restrict__ w_out,
                                                  const float* __restrict__ skip,
                                                  float* __restrict__ out) {
    gemm_nt(g_o, w_out, skip, out, TOK, DM, DM);
}

// ---------------- K3: rotary + permute qkv -> q,k,v in [b][h][i][j][e] ----------------
__global__ void k_rope(const float* __restrict__ pos) {
    int t = blockIdx.x;
    int b = t / (HH * WW);
    int ij = t - b * HH * WW;
    int i = ij / WW, j = ij - i * WW;
    int h = threadIdx.x >> 6, e = threadIdx.x & 63;

    const float* base = g_qkv + (size_t)t * (3 * DM);
    int out_idx = (((b * NHEAD + h) * HH + i) * WW + j) * EH + e;

    g_v[out_idx] = base[2 * DM + h * EH + e];

    float qv = base[0 * DM + h * EH + e];
    float kv = base[1 * DM + h * EH + e];
    float qo, ko;
    if (e < 32) {
        int u  = e & 15;            // 0..15 cos/sin index
        int fi = u & 7;             // freq index
        float f   = 3.14159265358979323846f * exp10f((float)fi * 0.125f);
        float p   = (u < 8) ? pos[(i * WW + j) * 2 + 0] : pos[(i * WW + j) * 2 + 1];
        float ang = p * f;
        float cs = cosf(ang), sn = sinf(ang);
        if (e < 16) {
            float q2 = base[0 * DM + h * EH + e + 16];
            float k2 = base[1 * DM + h * EH + e + 16];
            qo = qv * cs - q2 * sn;
            ko = kv * cs - k2 * sn;
        } else {
            float q1 = base[0 * DM + h * EH + e - 16];
            float k1 = base[1 * DM + h * EH + e - 16];
            qo = qv * cs + q1 * sn;
            ko = kv * cs + k1 * sn;
        }
    } else {
        qo = qv; ko = kv;
    }
    g_q[out_idx] = qo * 0.125f;     // / sqrt(64)
    g_k[out_idx] = ko;
}

// ---------------- K4: neighborhood attention, one warp per (b,h,i,j) ----------------
// block = 128 thr = 4 warps = 4 adjacent j (shared 7x7 windows overlap -> L1 reuse)
__global__ void __launch_bounds__(128) k_attn() {
    int jt = blockIdx.x;                 // 0..11
    int i  = blockIdx.y;                 // 0..47
    int bh = blockIdx.z;                 // 0..7
    int b = bh >> 2, h = bh & 3;
    int warp = threadIdx.x >> 5, lane = threadIdx.x & 31;
    int j = jt * 4 + warp;

    const float* kb = g_k + (size_t)(b * NHEAD + h) * HH * WW * EH;
    const float* vb = g_v + (size_t)(b * NHEAD + h) * HH * WW * EH;
    const float* qp = g_q + (size_t)(b * NHEAD + h) * HH * WW * EH + (i * WW + j) * EH;

    float2 q = *(const float2*)(qp + lane * 2);

    int sh = min(max(i - 3, 0), HH - 7);
    int sw = min(max(j - 3, 0), WW - 7);

    float s0 = -1e30f, s1 = -1e30f;
    int p = 0;
#pragma unroll
    for (int ph = 0; ph < 7; ph++) {
        const float* krow = kb + ((sh + ph) * WW + sw) * EH;
#pragma unroll
        for (int pw = 0; pw < 7; pw++) {
            float2 kv = *(const float2*)(krow + pw * EH + lane * 2);
            float d = q.x * kv.x + q.y * kv.y;
#pragma unroll
            for (int o = 16; o > 0; o >>= 1) d += __shfl_xor_sync(0xffffffffu, d, o);
            if (p < 32) { if (lane == p)      s0 = d; }
            else        { if (lane == p - 32) s1 = d; }
            p++;
        }
    }

    // softmax over 49 scores (lanes 0..31 hold s0 for p=lane; lanes 0..16 hold s1 for p=32+lane)
    float m = fmaxf(s0, s1);
#pragma unroll
    for (int o = 16; o > 0; o >>= 1) m = fmaxf(m, __shfl_xor_sync(0xffffffffu, m, o));
    float e0 = __expf(s0 - m);
    float e1 = (lane < 17) ? __expf(s1 - m) : 0.f;
    float sum = e0 + e1;
#pragma unroll
    for (int o = 16; o > 0; o >>= 1) sum += __shfl_xor_sync(0xffffffffu, sum, o);
    float inv = 1.f / sum;

    float2 acc = make_float2(0.f, 0.f);
    p = 0;
#pragma unroll
    for (int ph = 0; ph < 7; ph++) {
        const float* vrow = vb + ((sh + ph) * WW + sw) * EH;
#pragma unroll
        for (int pw = 0; pw < 7; pw++) {
            float a = (p < 32) ? __shfl_sync(0xffffffffu, e0, p)
                               : __shfl_sync(0xffffffffu, e1, p - 32);
            float2 vv = *(const float2*)(vrow + pw * EH + lane * 2);
            acc.x += a * vv.x;
            acc.y += a * vv.y;
            p++;
        }
    }
    acc.x *= inv; acc.y *= inv;

    // write [token][h*64 + e] for the output GEMM
    int tok = b * (HH * WW) + i * WW + j;
    float* op = g_o + (size_t)tok * DM + h * EH + lane * 2;
    *(float2*)op = acc;
}

// ---------------- launch ----------------
extern "C" void kernel_launch(void* const* d_in, const int* in_sizes, int n_in,
                              void* d_out, int out_size) {
    const float* x      = (const float*)d_in[0];
    const float* pos    = (const float*)d_in[1];
    const float* cond   = (const float*)d_in[2];
    const float* w_norm = (const float*)d_in[3];
    const float* w_qkv  = (const float*)d_in[4];
    const float* w_out  = (const float*)d_in[5];
    float* out = (float*)d_out;

    k_scale<<<NB, 256>>>(cond, w_norm);
    k_rms<<<TOK, 256>>>(x);

    dim3 g1((3 * DM) / 64, TOK / 64);
    k_gemm_qkv<<<g1, 256>>>(w_qkv);

    k_rope<<<TOK, 256>>>(pos);

    dim3 g2(WW / 4, HH, NB * NHEAD);
    k_attn<<<g2, 128>>>();

    dim3 g3(DM / 64, TOK / 64);
    k_gemm_out<<<g3, 256>>>(w_out, x, out);
}

// round 3
// speedup vs baseline: 1.1000x; 1.1000x over previous
#include <cuda_runtime.h>

#define TOK   4608      // n*H*W
#define NB    2
#define HH    48
#define WW    48
#define DM    256
#define NHEAD 4
#define EH    64
#define EPS   1e-6f

// ---------------- scratch (__device__ globals: allocation-free) ----------------
__device__ float g_scale[NB * DM];
__device__ float g_xn  [TOK * DM];
__device__ float g_qkv [TOK * 3 * DM];
__device__ float g_q   [NB * NHEAD * HH * WW * EH];
__device__ float g_k   [NB * NHEAD * HH * WW * EH];
__device__ float g_v   [NB * NHEAD * HH * WW * EH];
__device__ float g_o   [TOK * DM];

// ---------------- packed f32x2 helpers ----------------
__device__ __forceinline__ unsigned long long dupf(float x) {
    unsigned long long r;
    asm("mov.b64 %0,{%1,%2};" : "=l"(r) : "f"(x), "f"(x));
    return r;
}
__device__ __forceinline__ void ffma2(unsigned long long& c, unsigned long long a, unsigned long long b) {
    asm("fma.rn.f32x2 %0,%1,%2,%0;" : "+l"(c) : "l"(a), "l"(b));
}
__device__ __forceinline__ float2 unpk(unsigned long long v) {
    float2 r;
    asm("mov.b64 {%0,%1},%2;" : "=f"(r.x), "=f"(r.y) : "l"(v));
    return r;
}

// ---------------- K0: scale[b][c] = dot(cond[b], w_norm[c]) + 1 ----------------
__global__ void k_scale(const float* __restrict__ cond, const float* __restrict__ w_norm) {
    int b = blockIdx.x, c = threadIdx.x;
    const float4* cv = (const float4*)(cond + b * DM);
    const float4* wv = (const float4*)(w_norm + c * DM);
    float s = 0.f;
#pragma unroll 16
    for (int k = 0; k < DM / 4; k++) {
        float4 a = cv[k], w = wv[k];
        s += a.x * w.x + a.y * w.y + a.z * w.z + a.w * w.w;
    }
    g_scale[b * DM + c] = s + 1.f;
}

// ---------------- K1: RMS norm per token ----------------
__global__ void k_rms(const float* __restrict__ x) {
    int t = blockIdx.x;
    int c = threadIdx.x;
    int b = t / (HH * WW);
    float v = x[t * DM + c];
    float sq = v * v;
#pragma unroll
    for (int o = 16; o > 0; o >>= 1) sq += __shfl_xor_sync(0xffffffffu, sq, o);
    __shared__ float ws[8];
    if ((c & 31) == 0) ws[c >> 5] = sq;
    __syncthreads();
    float tot = ws[0] + ws[1] + ws[2] + ws[3] + ws[4] + ws[5] + ws[6] + ws[7];
    float inv = rsqrtf(tot * (1.f / DM) + EPS);
    g_xn[t * DM + c] = v * g_scale[b * DM + c] * inv;
}

// ---------------- FFMA2 tiled NT GEMM: C[M,N] = A[M,K]*B[N,K]^T (+Sk) ----------------
// BM=128, BK=16, BN in {128, 64}. 256 threads. Micro 8x(BN/16), acc packed f32x2.
// Smem is k-major (transposed on store) so compute loads are LDS.128 of packed pairs.
template<int BN>
__global__ void __launch_bounds__(256) k_gemm(const float* __restrict__ A,
                                              const float* __restrict__ B,
                                              const float* __restrict__ Sk,
                                              float* __restrict__ C,
                                              int M, int N, int K) {
    constexpr int BM = 128, BK = 16;
    constexpr int MICN = BN / 16;          // 8 or 4
    constexpr int NP   = MICN / 2;         // packed pairs per row
    __shared__ float As[2][BK][BM];
    __shared__ float Bs[2][BK][BN];

    int tid = threadIdx.x;
    int m0 = blockIdx.y * BM, n0 = blockIdx.x * BN;

    // gmem load mapping
    int arow = tid >> 1, akh = (tid & 1) * 8;                 // 128 rows x 8 k each
    int brow, bkh, bcnt;
    if (BN == 128) { brow = tid >> 1; bkh = (tid & 1) * 8; bcnt = 8; }
    else           { brow = tid >> 2; bkh = (tid & 3) * 4; bcnt = 4; }

    const float* Ag = A + (size_t)(m0 + arow) * K + akh;
    const float* Bg = B + (size_t)(n0 + brow) * K + bkh;

    float ra[8], rb[8];

    // prefetch tile 0
    {
        float4 v0 = *(const float4*)(Ag + 0);
        float4 v1 = *(const float4*)(Ag + 4);
        ra[0]=v0.x; ra[1]=v0.y; ra[2]=v0.z; ra[3]=v0.w;
        ra[4]=v1.x; ra[5]=v1.y; ra[6]=v1.z; ra[7]=v1.w;
        float4 w0 = *(const float4*)(Bg + 0);
        rb[0]=w0.x; rb[1]=w0.y; rb[2]=w0.z; rb[3]=w0.w;
        if (BN == 128) {
            float4 w1 = *(const float4*)(Bg + 4);
            rb[4]=w1.x; rb[5]=w1.y; rb[6]=w1.z; rb[7]=w1.w;
        }
    }
#pragma unroll
    for (int c = 0; c < 8; c++) As[0][akh + c][arow] = ra[c];
#pragma unroll
    for (int c = 0; c < 8; c++) if (c < bcnt) Bs[0][bkh + c][brow] = rb[c];
    __syncthreads();

    int tx = tid & 15, ty = tid >> 4;
    unsigned long long acc[8][NP];
#pragma unroll
    for (int i = 0; i < 8; i++)
#pragma unroll
        for (int j = 0; j < NP; j++) acc[i][j] = 0ull;

    int nkt = K / BK;
    int buf = 0;
    for (int t = 0; t < nkt; t++) {
        if (t + 1 < nkt) {
            int k0 = (t + 1) * BK;
            float4 v0 = *(const float4*)(Ag + k0);
            float4 v1 = *(const float4*)(Ag + k0 + 4);
            ra[0]=v0.x; ra[1]=v0.y; ra[2]=v0.z; ra[3]=v0.w;
            ra[4]=v1.x; ra[5]=v1.y; ra[6]=v1.z; ra[7]=v1.w;
            float4 w0 = *(const float4*)(Bg + k0);
            rb[0]=w0.x; rb[1]=w0.y; rb[2]=w0.z; rb[3]=w0.w;
            if (BN == 128) {
                float4 w1 = *(const float4*)(Bg + k0 + 4);
                rb[4]=w1.x; rb[5]=w1.y; rb[6]=w1.z; rb[7]=w1.w;
            }
        }
#pragma unroll
        for (int kk = 0; kk < BK; kk++) {
            float4 a0 = *(const float4*)&As[buf][kk][ty * 8];
            float4 a1 = *(const float4*)&As[buf][kk][ty * 8 + 4];
            unsigned long long bp[NP];
            {
                ulonglong2 b0 = *(const ulonglong2*)&Bs[buf][kk][tx * 4];
                bp[0] = b0.x; bp[1] = b0.y;
                if (BN == 128) {
                    ulonglong2 b1 = *(const ulonglong2*)&Bs[buf][kk][64 + tx * 4];
                    bp[2] = b1.x; bp[3] = b1.y;
                }
            }
            unsigned long long ad[8];
            ad[0]=dupf(a0.x); ad[1]=dupf(a0.y); ad[2]=dupf(a0.z); ad[3]=dupf(a0.w);
            ad[4]=dupf(a1.x); ad[5]=dupf(a1.y); ad[6]=dupf(a1.z); ad[7]=dupf(a1.w);
#pragma unroll
            for (int i = 0; i < 8; i++)
#pragma unroll
                for (int j = 0; j < NP; j++) ffma2(acc[i][j], ad[i], bp[j]);
        }
        if (t + 1 < nkt) {
            int nb = buf ^ 1;
#pragma unroll
            for (int c = 0; c < 8; c++) As[nb][akh + c][arow] = ra[c];
#pragma unroll
            for (int c = 0; c < 8; c++) if (c < bcnt) Bs[nb][bkh + c][brow] = rb[c];
            __syncthreads();
            buf = nb;
        }
    }

    // epilogue
#pragma unroll
    for (int i = 0; i < 8; i++) {
        int m = m0 + ty * 8 + i;
        {
            int nn = n0 + tx * 4;
            float2 p0 = unpk(acc[i][0]), p1 = unpk(acc[i][1]);
            float4 o = make_float4(p0.x, p0.y, p1.x, p1.y);
            if (Sk) {
                float4 s = *(const float4*)&Sk[(size_t)m * N + nn];
                o.x += s.x; o.y += s.y; o.z += s.z; o.w += s.w;
            }
            *(float4*)&C[(size_t)m * N + nn] = o;
        }
        if (BN == 128) {
            int nn = n0 + 64 + tx * 4;
            float2 p0 = unpk(acc[i][2]), p1 = unpk(acc[i][3]);
            float4 o = make_float4(p0.x, p0.y, p1.x, p1.y);
            if (Sk) {
                float4 s = *(const float4*)&Sk[(size_t)m * N + nn];
                o.x += s.x; o.y += s.y; o.z += s.z; o.w += s.w;
            }
            *(float4*)&C[(size_t)m * N + nn] = o;
        }
    }
}

// ---------------- K3: rotary + permute qkv -> q,k,v in [b][h][i][j][e] ----------------
__global__ void k_rope(const float* __restrict__ pos) {
    int t = blockIdx.x;
    int b = t / (HH * WW);
    int ij = t - b * HH * WW;
    int i = ij / WW, j = ij - i * WW;
    int h = threadIdx.x >> 6, e = threadIdx.x & 63;

    const float* base = g_qkv + (size_t)t * (3 * DM);
    int out_idx = (((b * NHEAD + h) * HH + i) * WW + j) * EH + e;

    g_v[out_idx] = base[2 * DM + h * EH + e];

    float qv = base[0 * DM + h * EH + e];
    float kv = base[1 * DM + h * EH + e];
    float qo, ko;
    if (e < 32) {
        int u  = e & 15;
        int fi = u & 7;
        float f   = 3.14159265358979323846f * exp10f((float)fi * 0.125f);
        float p   = (u < 8) ? pos[(i * WW + j) * 2 + 0] : pos[(i * WW + j) * 2 + 1];
        float ang = p * f;
        float cs = cosf(ang), sn = sinf(ang);
        if (e < 16) {
            float q2 = base[0 * DM + h * EH + e + 16];
            float k2 = base[1 * DM + h * EH + e + 16];
            qo = qv * cs - q2 * sn;
            ko = kv * cs - k2 * sn;
        } else {
            float q1 = base[0 * DM + h * EH + e - 16];
            float k1 = base[1 * DM + h * EH + e - 16];
            qo = qv * cs + q1 * sn;
            ko = kv * cs + k1 * sn;
        }
    } else {
        qo = qv; ko = kv;
    }
    g_q[out_idx] = qo * 0.125f;
    g_k[out_idx] = ko;
}

// ---------------- K4: neighborhood attention, one warp per (b,h,i,j) ----------------
__global__ void __launch_bounds__(128) k_attn() {
    int jt = blockIdx.x;
    int i  = blockIdx.y;
    int bh = blockIdx.z;
    int b = bh >> 2, h = bh & 3;
    int warp = threadIdx.x >> 5, lane = threadIdx.x & 31;
    int j = jt * 4 + warp;

    const float* kb = g_k + (size_t)(b * NHEAD + h) * HH * WW * EH;
    const float* vb = g_v + (size_t)(b * NHEAD + h) * HH * WW * EH;
    const float* qp = g_q + (size_t)(b * NHEAD + h) * HH * WW * EH + (i * WW + j) * EH;

    float2 q = *(const float2*)(qp + lane * 2);

    int sh = min(max(i - 3, 0), HH - 7);
    int sw = min(max(j - 3, 0), WW - 7);

    float s0 = -1e30f, s1 = -1e30f;
    int p = 0;
#pragma unroll
    for (int ph = 0; ph < 7; ph++) {
        const float* krow = kb + ((sh + ph) * WW + sw) * EH;
#pragma unroll
        for (int pw = 0; pw < 7; pw++) {
            float2 kv = *(const float2*)(krow + pw * EH + lane * 2);
            float d = q.x * kv.x + q.y * kv.y;
#pragma unroll
            for (int o = 16; o > 0; o >>= 1) d += __shfl_xor_sync(0xffffffffu, d, o);
            if (p < 32) { if (lane == p)      s0 = d; }
            else        { if (lane == p - 32) s1 = d; }
            p++;
        }
    }

    float m = fmaxf(s0, s1);
#pragma unroll
    for (int o = 16; o > 0; o >>= 1) m = fmaxf(m, __shfl_xor_sync(0xffffffffu, m, o));
    float e0 = __expf(s0 - m);
    float e1 = (lane < 17) ? __expf(s1 - m) : 0.f;
    float sum = e0 + e1;
#pragma unroll
    for (int o = 16; o > 0; o >>= 1) sum += __shfl_xor_sync(0xffffffffu, sum, o);
    float inv = 1.f / sum;

    float2 acc = make_float2(0.f, 0.f);
    p = 0;
#pragma unroll
    for (int ph = 0; ph < 7; ph++) {
        const float* vrow = vb + ((sh + ph) * WW + sw) * EH;
#pragma unroll
        for (int pw = 0; pw < 7; pw++) {
            float a = (p < 32) ? __shfl_sync(0xffffffffu, e0, p)
                               : __shfl_sync(0xffffffffu, e1, p - 32);
            float2 vv = *(const float2*)(vrow + pw * EH + lane * 2);
            acc.x += a * vv.x;
            acc.y += a * vv.y;
            p++;
        }
    }
    acc.x *= inv; acc.y *= inv;

    int tok = b * (HH * WW) + i * WW + j;
    float* op = g_o + (size_t)tok * DM + h * EH + lane * 2;
    *(float2*)op = acc;
}

// ---------------- launch ----------------
extern "C" void kernel_launch(void* const* d_in, const int* in_sizes, int n_in,
                              void* d_out, int out_size) {
    const float* x      = (const float*)d_in[0];
    const float* pos    = (const float*)d_in[1];
    const float* cond   = (const float*)d_in[2];
    const float* w_norm = (const float*)d_in[3];
    const float* w_qkv  = (const float*)d_in[4];
    const float* w_out  = (const float*)d_in[5];
    float* out = (float*)d_out;

    k_scale<<<NB, 256>>>(cond, w_norm);
    k_rms<<<TOK, 256>>>(x);

    {   // qkv: [4608,768] = g_xn[4608,256] @ w_qkv[768,256]^T
        float* gxn; cudaGetSymbolAddress((void**)&gxn, g_xn);
        float* gqkv; cudaGetSymbolAddress((void**)&gqkv, g_qkv);
        dim3 g1((3 * DM) / 128, TOK / 128);
        k_gemm<128><<<g1, 256>>>(gxn, w_qkv, nullptr, gqkv, TOK, 3 * DM, DM);
    }

    k_rope<<<TOK, 256>>>(pos);

    dim3 g2(WW / 4, HH, NB * NHEAD);
    k_attn<<<g2, 128>>>();

    {   // out: [4608,256] = g_o @ w_out^T + x
        float* go; cudaGetSymbolAddress((void**)&go, g_o);
        dim3 g3(DM / 64, TOK / 128);
        k_gemm<64><<<g3, 256>>>(go, w_out, x, out, TOK, DM, DM);
    }
}